// round 5
// baseline (speedup 1.0000x reference)
#include <cuda_runtime.h>
#include <cuda_bf16.h>
#include <cstdint>

// x:   [B=64, C=12, 224, 224] fp32
// w:   [C=12, E=768] fp32
// out: [B=64, P=196, E=768] fp32
//
// Two-kernel split:
//   K1: sum-pool x -> g_pooled[b*196+p][12]   (154 MB read, 0.6 MB write)
//   K2: [12544,12] x [12,768] -> out          (0.6 MB read, 38.5 MB write)

#define IMG   224
#define NP    14
#define C_IN  12
#define EMBED 768
#define NPATCH (64 * NP * NP)                   // 12544
#define POOL_THREADS (64 * C_IN * NP * 56)      // 602112
#define POOL_CTAS (POOL_THREADS / 256)          // 2352

__device__ __align__(16) float g_pooled[NPATCH * C_IN];

// ---------------- Kernel 1: streaming 16x16 sum-pool ----------------
// thread = (b, c, pi, q) with q = float4 column 0..55. Each thread reads 16
// independent float4 down its column (full coalesced 128B lines across the
// warp), reduces to a scalar, then 2 shuffles fold the 4 columns of a patch.
__global__ __launch_bounds__(256) void pool_kernel(const float* __restrict__ x)
{
    const int gid  = blockIdx.x * 256 + threadIdx.x;  // 0 .. 602111
    const int q    = gid % 56;
    const int r0   = gid / 56;
    const int pi   = r0 % NP;
    const int r1   = r0 / NP;
    const int c    = r1 % C_IN;
    const int b    = r1 / C_IN;

    const float4* base = reinterpret_cast<const float4*>(
        x + ((size_t)(b * C_IN + c) * IMG + (size_t)pi * 16) * IMG) + q;

    // 16 independent loads; 4 accumulators to keep the FADD chain short.
    float a0 = 0.f, a1 = 0.f, a2 = 0.f, a3 = 0.f;
    #pragma unroll
    for (int r = 0; r < 16; r += 4) {
        const float4 v0 = base[(size_t)(r + 0) * 56];
        const float4 v1 = base[(size_t)(r + 1) * 56];
        const float4 v2 = base[(size_t)(r + 2) * 56];
        const float4 v3 = base[(size_t)(r + 3) * 56];
        a0 += (v0.x + v0.y) + (v0.z + v0.w);
        a1 += (v1.x + v1.y) + (v1.z + v1.w);
        a2 += (v2.x + v2.y) + (v2.z + v2.w);
        a3 += (v3.x + v3.y) + (v3.z + v3.w);
    }
    float s = (a0 + a1) + (a2 + a3);

    // 56 % 4 == 0  =>  q ≡ gid (mod 4): the 4 lanes folded here are 4
    // consecutive gids sharing (b, c, pi) and never wrap the row.
    s += __shfl_xor_sync(0xffffffffu, s, 1);
    s += __shfl_xor_sync(0xffffffffu, s, 2);

    if ((q & 3) == 0) {
        const int pj = q >> 2;
        g_pooled[((size_t)b * (NP * NP) + pi * NP + pj) * C_IN + c] = s;
    }
}

// ---------------- Kernel 2: [12544,12] x [12,768] streaming matmul ----------------
// One CTA per patch. pooled row = 48 B broadcast (L2-hot), w L1-resident,
// each thread emits one float4 of the 3 KB output row.
__global__ __launch_bounds__(192) void embed_kernel(
    const float* __restrict__ w,
    float* __restrict__ out)
{
    const int bp  = blockIdx.x;      // 0 .. 12543
    const int e4  = threadIdx.x;     // float4 slot 0..191

    const float4* pr = reinterpret_cast<const float4*>(&g_pooled[(size_t)bp * C_IN]);
    const float4 p0 = pr[0], p1 = pr[1], p2 = pr[2];
    const float pc[C_IN] = { p0.x, p0.y, p0.z, p0.w,
                             p1.x, p1.y, p1.z, p1.w,
                             p2.x, p2.y, p2.z, p2.w };

    float4 acc = make_float4(0.f, 0.f, 0.f, 0.f);
    #pragma unroll
    for (int c = 0; c < C_IN; ++c) {
        const float4 wv = *reinterpret_cast<const float4*>(&w[c * EMBED + e4 * 4]);
        acc.x = fmaf(pc[c], wv.x, acc.x);
        acc.y = fmaf(pc[c], wv.y, acc.y);
        acc.z = fmaf(pc[c], wv.z, acc.z);
        acc.w = fmaf(pc[c], wv.w, acc.w);
    }

    *reinterpret_cast<float4*>(out + (size_t)bp * EMBED + e4 * 4) = acc;
}

extern "C" void kernel_launch(void* const* d_in, const int* in_sizes, int n_in,
                              void* d_out, int out_size)
{
    const float* x = (const float*)d_in[0];
    const float* w = (const float*)d_in[1];
    float* out = (float*)d_out;

    pool_kernel<<<POOL_CTAS, 256>>>(x);    // 2352 CTAs, 602112 threads
    embed_kernel<<<NPATCH, 192>>>(w, out); // 12544 CTAs
}

// round 6
// speedup vs baseline: 1.0353x; 1.0353x over previous
#include <cuda_runtime.h>
#include <cuda_bf16.h>
#include <cstdint>

// x:   [B=64, C=12, 224, 224] fp32
// w:   [C=12, E=768] fp32
// out: [B=64, P=196, E=768] fp32
//
// Fused persistent kernel. Work item = horizontally adjacent patch pair
// (16 rows x 32 cols x 12 channels = 24 KB, full 128B lines).
// Each thread register-caches w[:, e4] once; phase 2 is pure FFMA + 1 store.
// Next item's x loads are prefetched before the current item's barrier.

#define IMG    224
#define NP     14
#define C_IN   12
#define EMBED  768
#define NTH    384
#define NITEMS (64 * NP * 7)   // 6272 patch pairs
#define NCTAS  296             // 2 per SM

__global__ __launch_bounds__(NTH, 2) void fused_persistent_kernel(
    const float* __restrict__ x,
    const float* __restrict__ w,
    float* __restrict__ out)
{
    const int t    = threadIdx.x;
    const int warp = t >> 5;          // channel 0..11
    const int lane = t & 31;
    const int q8   = lane & 7;        // float4 column within 32-float pair row
    const int rh   = lane >> 3;       // row phase 0..3
    const int e4   = t % 192;         // output float4 slot
    const int jp   = t / 192;         // local patch 0/1 (uniform per warp)

    // ---- register-cache w[:, 4*e4 .. 4*e4+4) : 12 float4 ----
    float4 wreg[C_IN];
    #pragma unroll
    for (int c = 0; c < C_IN; ++c)
        wreg[c] = *reinterpret_cast<const float4*>(&w[c * EMBED + e4 * 4]);

    __shared__ float pooled[2][C_IN][2];

    int item = blockIdx.x;

    // prologue: load item's 4 float4 (rows rh, rh+4, rh+8, rh+12)
    float4 v0, v1, v2, v3;
    {
        const int pp = item % 7, rm = item / 7;
        const int pi = rm % NP,  b  = rm / NP;
        const float* p = x + (((size_t)(b * C_IN + warp)) * IMG + pi * 16 + rh) * IMG
                           + pp * 32 + q8 * 4;
        v0 = *reinterpret_cast<const float4*>(p);
        v1 = *reinterpret_cast<const float4*>(p + 4 * IMG);
        v2 = *reinterpret_cast<const float4*>(p + 8 * IMG);
        v3 = *reinterpret_cast<const float4*>(p + 12 * IMG);
    }

    int buf = 0;
    for (; item < NITEMS; item += NCTAS) {
        // ---- reduce current item ----
        float s = ((v0.x + v0.y) + (v0.z + v0.w))
                + ((v1.x + v1.y) + (v1.z + v1.w))
                + ((v2.x + v2.y) + (v2.z + v2.w))
                + ((v3.x + v3.y) + (v3.z + v3.w));

        // ---- prefetch next item (independent of reduce/phase-2) ----
        const int nxt = item + NCTAS;
        if (nxt < NITEMS) {
            const int pp = nxt % 7, rm = nxt / 7;
            const int pi = rm % NP, b  = rm / NP;
            const float* p = x + (((size_t)(b * C_IN + warp)) * IMG + pi * 16 + rh) * IMG
                               + pp * 32 + q8 * 4;
            v0 = *reinterpret_cast<const float4*>(p);
            v1 = *reinterpret_cast<const float4*>(p + 4 * IMG);
            v2 = *reinterpret_cast<const float4*>(p + 8 * IMG);
            v3 = *reinterpret_cast<const float4*>(p + 12 * IMG);
        }

        // fold cols within patch (lane bits 0,1) and row phases (bits 3,4);
        // bit 2 = patch select survives.
        s += __shfl_xor_sync(0xffffffffu, s, 1);
        s += __shfl_xor_sync(0xffffffffu, s, 2);
        s += __shfl_xor_sync(0xffffffffu, s, 8);
        s += __shfl_xor_sync(0xffffffffu, s, 16);
        if ((lane & 27) == 0)
            pooled[buf][warp][(lane >> 2) & 1] = s;
        __syncthreads();

        // ---- phase 2: 12 register FFMAs, one float4 store ----
        float4 acc = make_float4(0.f, 0.f, 0.f, 0.f);
        #pragma unroll
        for (int c = 0; c < C_IN; ++c) {
            const float pc = pooled[buf][c][jp];
            acc.x = fmaf(pc, wreg[c].x, acc.x);
            acc.y = fmaf(pc, wreg[c].y, acc.y);
            acc.z = fmaf(pc, wreg[c].z, acc.z);
            acc.w = fmaf(pc, wreg[c].w, acc.w);
        }

        const int pp = item % 7, rm = item / 7;
        const int pi = rm % NP,  b  = rm / NP;
        float* o = out + (((size_t)b * (NP * NP)) + pi * NP + pp * 2 + jp) * EMBED + e4 * 4;
        *reinterpret_cast<float4*>(o) = acc;

        buf ^= 1;   // double-buffered pooled: one barrier per iteration is enough
    }
}

extern "C" void kernel_launch(void* const* d_in, const int* in_sizes, int n_in,
                              void* d_out, int out_size)
{
    const float* x = (const float*)d_in[0];
    const float* w = (const float*)d_in[1];
    float* out = (float*)d_out;

    fused_persistent_kernel<<<NCTAS, NTH>>>(x, w, out);
}

// round 7
// speedup vs baseline: 1.4536x; 1.4041x over previous
#include <cuda_runtime.h>
#include <cuda_bf16.h>
#include <cstdint>

// x:   [B=64, C=12, 224, 224] fp32
// w:   [C=12, E=768] fp32
// out: [B=64, P=196, E=768] fp32
//
// CTA = 2x2 patch block (32x32 pixels x 12 channels = 48 KB of x).
// Phase 1: warp = channel, 8 independent full-line float4 loads per thread,
//          dual shuffle-reduce -> pooled[12][4].
// Phase 2: each thread loads w[:, e4] once (12 LDG.128) and emits TWO patch
//          outputs from it (w L1 traffic halved vs one-output-per-thread).

#define IMG    224
#define NP     14
#define C_IN   12
#define EMBED  768
#define NTH    384

__global__ __launch_bounds__(NTH, 3) void patch_block_kernel(
    const float* __restrict__ x,
    const float* __restrict__ w,
    float* __restrict__ out)
{
    const int pp  = blockIdx.x;        // patch-col pair 0..6
    const int pr  = blockIdx.y;        // patch-row pair 0..6
    const int b   = blockIdx.z;        // 0..63
    const int t   = threadIdx.x;
    const int warp = t >> 5;           // channel 0..11
    const int lane = t & 31;
    const int q8  = lane & 7;          // float4 col within the 32-float row
    const int rh  = lane >> 3;         // row phase 0..3

    __shared__ float pooled[C_IN][4];  // [channel][prow*2 + pcol]

    // ---- Phase 1: pool a 32x32 region of channel `warp` ----
    // Thread loads rows rh + 4k (k=0..7) at float4-col q8: 8 independent
    // LDG.128, each warp row segment = 128 B line. k<4 -> top patch row.
    const float* base = x
        + (((size_t)(b * C_IN + warp)) * IMG + (size_t)pr * 32 + rh) * IMG
        + (size_t)pp * 32 + q8 * 4;

    float4 u0 = *reinterpret_cast<const float4*>(base + (size_t)(4 * 0) * IMG);
    float4 u1 = *reinterpret_cast<const float4*>(base + (size_t)(4 * 1) * IMG);
    float4 u2 = *reinterpret_cast<const float4*>(base + (size_t)(4 * 2) * IMG);
    float4 u3 = *reinterpret_cast<const float4*>(base + (size_t)(4 * 3) * IMG);
    float4 d0 = *reinterpret_cast<const float4*>(base + (size_t)(4 * 4) * IMG);
    float4 d1 = *reinterpret_cast<const float4*>(base + (size_t)(4 * 5) * IMG);
    float4 d2 = *reinterpret_cast<const float4*>(base + (size_t)(4 * 6) * IMG);
    float4 d3 = *reinterpret_cast<const float4*>(base + (size_t)(4 * 7) * IMG);

    float st = (((u0.x + u0.y) + (u0.z + u0.w)) + ((u1.x + u1.y) + (u1.z + u1.w)))
             + (((u2.x + u2.y) + (u2.z + u2.w)) + ((u3.x + u3.y) + (u3.z + u3.w)));
    float sb = (((d0.x + d0.y) + (d0.z + d0.w)) + ((d1.x + d1.y) + (d1.z + d1.w)))
             + (((d2.x + d2.y) + (d2.z + d2.w)) + ((d3.x + d3.y) + (d3.z + d3.w)));

    // Fold lane bits 0,1 (float4 cols within a patch) and 3,4 (row phases);
    // bit 2 (q8>>2) = patch column survives.
    st += __shfl_xor_sync(0xffffffffu, st, 1);
    sb += __shfl_xor_sync(0xffffffffu, sb, 1);
    st += __shfl_xor_sync(0xffffffffu, st, 2);
    sb += __shfl_xor_sync(0xffffffffu, sb, 2);
    st += __shfl_xor_sync(0xffffffffu, st, 8);
    sb += __shfl_xor_sync(0xffffffffu, sb, 8);
    st += __shfl_xor_sync(0xffffffffu, st, 16);
    sb += __shfl_xor_sync(0xffffffffu, sb, 16);

    if ((lane & 27) == 0) {            // lanes 0 and 4
        const int pc = (lane >> 2) & 1;
        pooled[warp][pc]     = st;     // top patch row
        pooled[warp][2 + pc] = sb;     // bottom patch row
    }
    __syncthreads();

    // ---- Phase 2: one w column read serves two patch outputs ----
    const int e4 = t % 192;            // output float4 slot
    const int lr = t / 192;            // local patch row 0/1 (uniform per warp)

    float4 acc0 = make_float4(0.f, 0.f, 0.f, 0.f);  // patch col 0
    float4 acc1 = make_float4(0.f, 0.f, 0.f, 0.f);  // patch col 1
    #pragma unroll
    for (int c = 0; c < C_IN; ++c) {
        const float4 wv = *reinterpret_cast<const float4*>(&w[c * EMBED + e4 * 4]);
        const float p0 = pooled[c][lr * 2 + 0];
        const float p1 = pooled[c][lr * 2 + 1];
        acc0.x = fmaf(p0, wv.x, acc0.x);  acc1.x = fmaf(p1, wv.x, acc1.x);
        acc0.y = fmaf(p0, wv.y, acc0.y);  acc1.y = fmaf(p1, wv.y, acc1.y);
        acc0.z = fmaf(p0, wv.z, acc0.z);  acc1.z = fmaf(p1, wv.z, acc1.z);
        acc0.w = fmaf(p0, wv.w, acc0.w);  acc1.w = fmaf(p1, wv.w, acc1.w);
    }

    const int pi = pr * 2 + lr;        // global patch row
    const int pj = pp * 2;             // global patch col (even)
    float* o = out + ((size_t)b * (NP * NP) + (size_t)pi * NP + pj) * EMBED + e4 * 4;
    *reinterpret_cast<float4*>(o)         = acc0;   // patch (pi, pj)
    *reinterpret_cast<float4*>(o + EMBED) = acc1;   // patch (pi, pj+1)
}

extern "C" void kernel_launch(void* const* d_in, const int* in_sizes, int n_in,
                              void* d_out, int out_size)
{
    const float* x = (const float*)d_in[0];
    const float* w = (const float*)d_in[1];
    float* out = (float*)d_out;

    dim3 grid(7, 7, 64);   // 3136 CTAs
    patch_block_kernel<<<grid, NTH>>>(x, w, out);
}